// round 6
// baseline (speedup 1.0000x reference)
#include <cuda_runtime.h>
#include <math.h>
#include <stdint.h>

// Problem constants
#define BSZ   64
#define LSEQ  100
#define LP1   101
#define DIM   64
#define NCOL  (BSZ * LP1)   // 6464
#define NROW  (BSZ * LSEQ)  // 6400
#define NCOLP 6656          // padded compacted-col bound (52 * 128)
#define NEG10K (-10000.0f)
#define LOG2E 1.4426950408889634f

#define NCH   6             // N chunk-slices (grid.y)
#define NSL   (NCH * 4)     // partS slices (4 warp col-groups per CTA) = 24
#define TILEF 8192          // floats per 128x64 fragment tile
#define TILEB (TILEF * 4)   // 32 KB

// ---------------- scratch (__device__ globals; no allocs) ----------------
__device__ int    g_nv;
__device__ int    g_colid[NCOL];
__device__ int    g_itemid[NCOL];
__device__ float  g_addterm[NCOL];        // -log2(pop) per compacted column
__device__ float  g_keep[BSZ * NCOLP];    // -log2(pop) or -inf per (batch, padded col)
__device__ float  g_Afrag[NROW * DIM];    // tf32(prec*log2e) in mma-fragment order
__device__ float  g_Bfrag[NCOLP * DIM];   // tf32 compacted embs in mma-fragment order
__device__ float  g_tgt[NROW];
__device__ float  g_partS[NROW * NSL];    // row-major [row][slice]
__device__ double g_rn[32];
__device__ double g_rd[32];

// ---------------- PTX helpers ----------------
__device__ __forceinline__ uint32_t smem_u32(const void* p) {
    uint32_t a;
    asm("{ .reg .u64 t; cvta.to.shared.u64 t, %1; cvt.u32.u64 %0, t; }" : "=r"(a) : "l"(p));
    return a;
}
__device__ __forceinline__ uint32_t f2tf(float x) {  // fp32 -> tf32 round-to-nearest
    uint32_t u;
    asm("cvt.rna.tf32.f32 %0, %1;" : "=r"(u) : "f"(x));
    return u;
}
__device__ __forceinline__ float ex2f(float x) {     // 2^x, -inf -> 0
    float y;
    asm("ex2.approx.f32 %0, %1;" : "=f"(y) : "f"(x));
    return y;
}
__device__ __forceinline__ void cp16(uint32_t dst, const void* src) {
    asm volatile("cp.async.ca.shared.global [%0], [%1], 16;" :: "r"(dst), "l"(src) : "memory");
}
#define CP_COMMIT()  asm volatile("cp.async.commit_group;" ::: "memory")
#define CP_WAIT0()   asm volatile("cp.async.wait_group 0;" ::: "memory")
#define CP_WAIT1()   asm volatile("cp.async.wait_group 1;" ::: "memory")
#define CP_WAIT2()   asm volatile("cp.async.wait_group 2;" ::: "memory")

__device__ __forceinline__ void mma8(float* c, uint32_t a0, uint32_t a1, uint32_t a2,
                                     uint32_t a3, uint32_t b0, uint32_t b1) {
    asm volatile("mma.sync.aligned.m16n8k8.row.col.f32.tf32.tf32.f32 "
        "{%0,%1,%2,%3}, {%4,%5,%6,%7}, {%8,%9}, {%0,%1,%2,%3};"
        : "+f"(c[0]), "+f"(c[1]), "+f"(c[2]), "+f"(c[3])
        : "r"(a0), "r"(a1), "r"(a2), "r"(a3), "r"(b0), "r"(b1));
}

// ---------------------------------------------------------------------------
// 1) Compact valid columns — warp-per-2-batches, 2 block syncs total.
// ---------------------------------------------------------------------------
__global__ void compact_kernel(const int* __restrict__ log_mask,
                               const int* __restrict__ items,
                               const float* __restrict__ pop) {
    __shared__ int cnt[64];
    __shared__ int off[64];
    int t = threadIdx.x, w = t >> 5, lane = t & 31;

    #pragma unroll
    for (int s = 0; s < 2; s++) {
        int b = 2 * w + s;
        int c = 0;
        #pragma unroll
        for (int ch = 0; ch < 4; ch++) {
            int pos = ch * 32 + lane;
            int flag = 0;
            if (pos <= LSEQ) flag = (pos == LSEQ) ? 1 : (log_mask[b * LSEQ + pos] != 0);
            c += __popc(__ballot_sync(0xffffffffu, flag));
        }
        if (lane == 0) cnt[b] = c;
    }
    __syncthreads();

    if (w == 0) {
        int c0 = cnt[2 * lane], c1 = cnt[2 * lane + 1];
        int s = c0 + c1, sc = s;
        #pragma unroll
        for (int o = 1; o < 32; o <<= 1) {
            int u = __shfl_up_sync(0xffffffffu, sc, o);
            if (lane >= o) sc += u;
        }
        int base = sc - s;
        off[2 * lane] = base;
        off[2 * lane + 1] = base + c0;
        if (lane == 31) g_nv = sc;
    }
    __syncthreads();

    #pragma unroll
    for (int s = 0; s < 2; s++) {
        int b = 2 * w + s;
        int o = off[b];
        #pragma unroll
        for (int ch = 0; ch < 4; ch++) {
            int pos = ch * 32 + lane;
            int flag = 0;
            if (pos <= LSEQ) flag = (pos == LSEQ) ? 1 : (log_mask[b * LSEQ + pos] != 0);
            unsigned bal = __ballot_sync(0xffffffffu, flag);
            if (flag) {
                int slot = o + __popc(bal & ((1u << lane) - 1u));
                int k = b * LP1 + pos;
                g_colid[slot] = k;
                int id = items[k];
                g_itemid[slot] = id;
                g_addterm[slot] = -log2f(pop[id]);
            }
            o += __popc(bal);
        }
    }
}

// ---------------------------------------------------------------------------
// 2) Fused dup-mask + fragment-prep + target (all depend only on compact).
// ---------------------------------------------------------------------------
#define AB_BLK  (NROW * 16 / 512)    // 200
#define BB_BLK  (NCOLP * 16 / 512)   // 208
#define TG_BLK  (NROW / 64)          // 100
#define FUSE_BLOCKS (BSZ + AB_BLK + BB_BLK + TG_BLK)

__global__ void dupprep_kernel(const int* __restrict__ items,
                               const float* __restrict__ prec,
                               const float* __restrict__ embs,
                               const float* __restrict__ pop,
                               const int* __restrict__ log_mask) {
    int blk = blockIdx.x;
    int t = threadIdx.x;
    if (blk < BSZ) {
        __shared__ int ids[LP1];
        int i = blk;
        if (t < LP1) ids[t] = items[i * LP1 + t];
        __syncthreads();
        int nv = g_nv;
        int nvp = (nv + 127) & ~127;
        const float NINF = __int_as_float(0xff800000);
        for (int kv = t; kv < nvp; kv += 512) {
            float out = NINF;
            if (kv < nv) {
                int id = g_itemid[kv];
                bool dup = false;
                #pragma unroll 4
                for (int j = 0; j < LP1; j++) dup |= (id == ids[j]);
                out = dup ? NINF : g_addterm[kv];
            }
            g_keep[i * NCOLP + kv] = out;
        }
    } else if (blk < BSZ + AB_BLK) {
        // A fragments: idx -> (mt128, rg, mt01, kt, lane); 4 floats per thread
        int iA = (blk - BSZ) * 512 + t;
        int lane = iA & 31;
        int kt = (iA >> 5) & 7;
        int mt01 = (iA >> 8) & 1;
        int rg = (iA >> 9) & 3;
        int mt128 = iA >> 11;
        int g = lane >> 2, tig = lane & 3;
        int r0 = mt128 * 128 + rg * 32 + mt01 * 16 + g;
        int k0 = kt * 8 + tig;
        float4 u;
        u.x = prec[r0 * DIM + k0] * LOG2E;
        u.y = prec[(r0 + 8) * DIM + k0] * LOG2E;
        u.z = prec[r0 * DIM + k0 + 4] * LOG2E;
        u.w = prec[(r0 + 8) * DIM + k0 + 4] * LOG2E;
        uint4 v = make_uint4(f2tf(u.x), f2tf(u.y), f2tf(u.z), f2tf(u.w));
        ((uint4*)g_Afrag)[iA] = v;
    } else if (blk < BSZ + AB_BLK + BB_BLK) {
        // B fragments: idx -> (ktile, cc, kt, lane)
        int iB = (blk - BSZ - AB_BLK) * 512 + t;
        int lane = iB & 31;
        int kt = (iB >> 5) & 7;
        int cc = (iB >> 8) & 7;
        int ktile = iB >> 11;
        int g = lane >> 2, tig = lane & 3;
        int nv = g_nv;
        int c0 = ktile * 128 + cc * 16 + g;
        int c1 = c0 + 8;
        int k0 = kt * 8 + tig;
        uint4 v = make_uint4(0u, 0u, 0u, 0u);
        if (c0 < nv) {
            const float* e = embs + g_colid[c0] * DIM;
            v.x = f2tf(e[k0]);
            v.y = f2tf(e[k0 + 4]);
        }
        if (c1 < nv) {
            const float* e = embs + g_colid[c1] * DIM;
            v.z = f2tf(e[k0]);
            v.w = f2tf(e[k0 + 4]);
        }
        ((uint4*)g_Bfrag)[iB] = v;
    } else {
        // target logits: 8 threads per row, 64 rows per block
        int rloc = t >> 3, sub = t & 7;
        int r = (blk - BSZ - AB_BLK - BB_BLK) * 64 + rloc;
        int i = r / LSEQ, j = r - i * LSEQ;
        int pos = j + 1;
        int valid = (pos == LSEQ) ? 1 : (log_mask[i * LSEQ + pos] != 0);
        int tc = i * LP1 + pos;
        const float4* p4 = (const float4*)(prec + r * DIM);
        const float4* e4 = (const float4*)(embs + tc * DIM);
        float4 a0 = p4[sub], b0 = e4[sub], a1 = p4[sub + 8], b1 = e4[sub + 8];
        float s = a0.x * b0.x + a0.y * b0.y + a0.z * b0.z + a0.w * b0.w
                + a1.x * b1.x + a1.y * b1.y + a1.z * b1.z + a1.w * b1.w;
        s += __shfl_down_sync(0xffffffffu, s, 4);
        s += __shfl_down_sync(0xffffffffu, s, 2);
        s += __shfl_down_sync(0xffffffffu, s, 1);
        if (sub == 0) g_tgt[r] = valid ? (s - logf(pop[items[tc]])) : NEG10K;
    }
}

// ---------------------------------------------------------------------------
// 3) Main: tf32 mma.sync GEMM, fragment LDS.128 operands (A reloaded per kt —
//    no register spills), fused exp2 row-sums. 512 threads, 3-deep ring.
// ---------------------------------------------------------------------------
#define SMEM_BYTES (4 * TILEB + 3 * 1536)

__global__ __launch_bounds__(512, 1)
void main_kernel() {
    extern __shared__ float sm[];
    float* As = sm;
    float* Bsb[3] = {sm + TILEF, sm + 2 * TILEF, sm + 3 * TILEF};
    float* Ksb[3] = {sm + 4 * TILEF, sm + 4 * TILEF + 384, sm + 4 * TILEF + 768};
    const uint32_t su = smem_u32(sm);
    const uint32_t Bu[3] = {su + TILEB, su + 2 * TILEB, su + 3 * TILEB};
    const uint32_t Ku[3] = {su + 4 * TILEB, su + 4 * TILEB + 1536, su + 4 * TILEB + 3072};

    const int t = threadIdx.x;
    const int w = t >> 5, lane = t & 31;
    const int g = lane >> 2, tig = lane & 3;
    const int rg = w >> 2;                   // row group 0..3 (32 rows each)
    const int wcol = w & 3;                  // col group 0..3 (32 cols each)
    const int m0 = blockIdx.x * 128;
    const int ch = blockIdx.y;
    const int nv = g_nv;
    const int T = (nv + 127) >> 7;
    const int ntiles = (T > ch) ? ((T - ch + NCH - 1) / NCH) : 0;
    const int bfirst = m0 / LSEQ;
    const int slice = ch * 4 + wcol;

    int bl[2][2];
    #pragma unroll
    for (int mt = 0; mt < 2; mt++)
        #pragma unroll
        for (int h = 0; h < 2; h++)
            bl[mt][h] = (m0 + rg * 32 + mt * 16 + g + h * 8) / LSEQ - bfirst;

    float rs[4] = {0.f, 0.f, 0.f, 0.f};

    if (ntiles == 0) {
        if (tig == 0) {
            #pragma unroll
            for (int mt = 0; mt < 2; mt++)
                #pragma unroll
                for (int h = 0; h < 2; h++)
                    g_partS[(m0 + rg * 32 + mt * 16 + g + h * 8) * NSL + slice] = 0.f;
        }
        return;
    }

    auto stageB = [&](int tile, int buf) {
        const float* Bg = g_Bfrag + (size_t)tile * TILEF;
        #pragma unroll
        for (int i = 0; i < 4; i++) {
            int idx = t + i * 512;
            cp16(Bu[buf] + idx * 16, Bg + idx * 4);
        }
        if (t < 96) {
            int b = t >> 5, q = t & 31;
            int bg = min(bfirst + b, BSZ - 1);
            cp16(Ku[buf] + (b * 128 + q * 4) * 4, g_keep + (size_t)bg * NCOLP + tile * 128 + q * 4);
        }
    };

    // prologue: stage A + up to 3 B tiles
    {
        const float* Ag = g_Afrag + (size_t)m0 * DIM;
        #pragma unroll
        for (int i = 0; i < 4; i++) {
            int idx = t + i * 512;
            cp16(su + idx * 16, Ag + idx * 4);
        }
    }
    stageB(ch, 0);
    CP_COMMIT();
    int committed = 1;
    if (ntiles > 1) { stageB(ch + NCH, 1); CP_COMMIT(); committed = 2; }
    if (ntiles > 2) { stageB(ch + 2 * NCH, 2); CP_COMMIT(); committed = 3; }

    // per-warp A fragment base pointers (reloaded from smem every kt — keeps
    // live registers ~70, no spills at 512 threads)
    const float4* ap0 = (const float4*)As + (rg * 2 + 0) * 256 + lane;
    const float4* ap1 = (const float4*)As + (rg * 2 + 1) * 256 + lane;

    for (int ti = 0; ti < ntiles; ti++) {
        int rem = committed - ti - 1;
        if (rem >= 2) CP_WAIT2(); else if (rem == 1) CP_WAIT1(); else CP_WAIT0();
        __syncthreads();

        int buf = ti - (ti / 3) * 3;
        const float* B = Bsb[buf];
        const float* KP = Ksb[buf];

        #pragma unroll
        for (int cc2 = 0; cc2 < 2; cc2++) {
            const int cc = wcol * 2 + cc2;
            const float4* bp = (const float4*)(B + cc * 1024) + lane;
            float c[2][2][4];
            #pragma unroll
            for (int mt = 0; mt < 2; mt++)
                #pragma unroll
                for (int nt = 0; nt < 2; nt++)
                    #pragma unroll
                    for (int q = 0; q < 4; q++) c[mt][nt][q] = 0.f;

            #pragma unroll
            for (int kt = 0; kt < 8; kt++) {
                float4 a0 = ap0[kt * 32];
                float4 a1 = ap1[kt * 32];
                float4 b = bp[kt * 32];
                uint32_t bx = __float_as_uint(b.x), by = __float_as_uint(b.y);
                uint32_t bz = __float_as_uint(b.z), bw_ = __float_as_uint(b.w);
                mma8(c[0][0], __float_as_uint(a0.x), __float_as_uint(a0.y),
                              __float_as_uint(a0.z), __float_as_uint(a0.w), bx, by);
                mma8(c[0][1], __float_as_uint(a0.x), __float_as_uint(a0.y),
                              __float_as_uint(a0.z), __float_as_uint(a0.w), bz, bw_);
                mma8(c[1][0], __float_as_uint(a1.x), __float_as_uint(a1.y),
                              __float_as_uint(a1.z), __float_as_uint(a1.w), bx, by);
                mma8(c[1][1], __float_as_uint(a1.x), __float_as_uint(a1.y),
                              __float_as_uint(a1.z), __float_as_uint(a1.w), bz, bw_);
            }

            const int C = cc * 16;
            #pragma unroll
            for (int mt = 0; mt < 2; mt++) {
                #pragma unroll
                for (int nt = 0; nt < 2; nt++) {
                    int col = C + nt * 8 + 2 * tig;
                    float2 k0 = *(const float2*)(KP + bl[mt][0] * 128 + col);
                    float2 k1 = *(const float2*)(KP + bl[mt][1] * 128 + col);
                    rs[mt * 2 + 0] += ex2f(c[mt][nt][0] + k0.x) + ex2f(c[mt][nt][1] + k0.y);
                    rs[mt * 2 + 1] += ex2f(c[mt][nt][2] + k1.x) + ex2f(c[mt][nt][3] + k1.y);
                }
            }
        }

        __syncthreads();
        if (ti + 3 < ntiles) { stageB(ch + (ti + 3) * NCH, buf); CP_COMMIT(); committed++; }
    }

    // reduce over the 4 tig lanes of each row
    #pragma unroll
    for (int q = 0; q < 4; q++) {
        rs[q] += __shfl_xor_sync(0xffffffffu, rs[q], 1);
        rs[q] += __shfl_xor_sync(0xffffffffu, rs[q], 2);
    }
    if (tig == 0) {
        #pragma unroll
        for (int mt = 0; mt < 2; mt++)
            #pragma unroll
            for (int h = 0; h < 2; h++)
                g_partS[(m0 + rg * 32 + mt * 16 + g + h * 8) * NSL + slice] = rs[mt * 2 + h];
    }
}

// ---------------------------------------------------------------------------
// 4) Two-stage deterministic reduction — one thread per row, contiguous reads
// ---------------------------------------------------------------------------
__global__ void reduce1_kernel(const int* __restrict__ log_mask) {
    __shared__ double sn[256];
    __shared__ double sd[256];
    int t = threadIdx.x;
    int r = blockIdx.x * 256 + t;
    const float4* p = (const float4*)(g_partS + (size_t)r * NSL);
    float S = 0.f;
    #pragma unroll
    for (int i = 0; i < NSL / 4; i++) {
        float4 v = p[i];
        S += (v.x + v.y) + (v.z + v.w);
    }
    float tv = g_tgt[r];
    S += __expf(tv);
    float nll = (S > 0.f) ? (logf(S) - tv) : logf((float)NCOL);
    bool wv = (log_mask[r] != 0);
    sn[t] = wv ? (double)nll : 0.0;
    sd[t] = wv ? 1.0 : 0.0;
    __syncthreads();
    for (int o = 128; o > 0; o >>= 1) {
        if (t < o) { sn[t] += sn[t + o]; sd[t] += sd[t + o]; }
        __syncthreads();
    }
    if (t == 0) { g_rn[blockIdx.x] = sn[0]; g_rd[blockIdx.x] = sd[0]; }
}

__global__ void reduce2_kernel(float* __restrict__ out) {
    __shared__ double sn[32];
    __shared__ double sd[32];
    int t = threadIdx.x;
    sn[t] = (t < 25) ? g_rn[t] : 0.0;
    sd[t] = (t < 25) ? g_rd[t] : 0.0;
    __syncthreads();
    for (int o = 16; o > 0; o >>= 1) {
        if (t < o) { sn[t] += sn[t + o]; sd[t] += sd[t + o]; }
        __syncthreads();
    }
    if (t == 0) out[0] = (float)(sn[0] / sd[0]);
}

// ---------------------------------------------------------------------------
extern "C" void kernel_launch(void* const* d_in, const int* in_sizes, int n_in,
                              void* d_out, int out_size) {
    const float* prec  = (const float*)d_in[0];  // [6400, 64]
    const float* embs  = (const float*)d_in[1];  // [6464, 64]
    const float* pop   = (const float*)d_in[2];  // [100001]
    const int*   items = (const int*)d_in[3];    // [6464]
    const int*   lmask = (const int*)d_in[4];    // [64, 100]
    float* out = (float*)d_out;

    cudaFuncSetAttribute(main_kernel, cudaFuncAttributeMaxDynamicSharedMemorySize,
                         SMEM_BYTES);

    compact_kernel<<<1, 1024>>>(lmask, items, pop);
    dupprep_kernel<<<FUSE_BLOCKS, 512>>>(items, prec, embs, pop, lmask);
    main_kernel<<<dim3(NROW / 128, NCH), 512, SMEM_BYTES>>>();
    reduce1_kernel<<<NROW / 256, 256>>>(lmask);
    reduce2_kernel<<<1, 32>>>(out);
}

// round 7
// speedup vs baseline: 1.1304x; 1.1304x over previous
#include <cuda_runtime.h>
#include <cuda_bf16.h>
#include <math.h>
#include <stdint.h>

// Problem constants
#define BSZ   64
#define LSEQ  100
#define LP1   101
#define DIM   64
#define NCOL  (BSZ * LP1)   // 6464
#define NROW  (BSZ * LSEQ)  // 6400
#define NCOLP 6656          // padded compacted-col bound (52 * 128)
#define NEG10K (-10000.0f)
#define LOG2E 1.4426950408889634f
#define NCH   6             // N chunk-slices (grid.y); partS slices = NCH

// ---------------- scratch (__device__ globals; no allocs) ----------------
__device__ int    g_nv;
__device__ int    g_colid[NCOL];
__device__ int    g_itemid[NCOL];
__device__ float  g_addterm[NCOL];        // -log2(pop) per compacted column
__device__ float  g_keep[BSZ * NCOLP];    // -log2(pop) or -inf per (batch, padded col)
__device__ uint4  g_Afrag4[NROW * 8];     // bf16(prec*log2e), m16n8k16 fragment order
__device__ uint4  g_Bfrag4[NCOLP * 8];    // bf16 compacted embs, fragment order
__device__ float  g_tgt[NROW];
__device__ float  g_partS[NROW * NCH];    // row-major [row][chunk]
__device__ double g_rn[32];
__device__ double g_rd[32];

// ---------------- PTX helpers ----------------
__device__ __forceinline__ uint32_t smem_u32(const void* p) {
    uint32_t a;
    asm("{ .reg .u64 t; cvta.to.shared.u64 t, %1; cvt.u32.u64 %0, t; }" : "=r"(a) : "l"(p));
    return a;
}
__device__ __forceinline__ uint32_t pk2(float lo, float hi) {  // bf16x2, RN (unbiased)
    __nv_bfloat162 h = __floats2bfloat162_rn(lo, hi);          // .x = low half
    return *(uint32_t*)&h;
}
__device__ __forceinline__ float ex2f(float x) {               // 2^x, -inf -> 0
    float y;
    asm("ex2.approx.f32 %0, %1;" : "=f"(y) : "f"(x));
    return y;
}
__device__ __forceinline__ void cp16(uint32_t dst, const void* src) {
    asm volatile("cp.async.ca.shared.global [%0], [%1], 16;" :: "r"(dst), "l"(src) : "memory");
}
#define CP_COMMIT()  asm volatile("cp.async.commit_group;" ::: "memory")
#define CP_WAIT0()   asm volatile("cp.async.wait_group 0;" ::: "memory")
#define CP_WAIT1()   asm volatile("cp.async.wait_group 1;" ::: "memory")
#define CP_WAIT2()   asm volatile("cp.async.wait_group 2;" ::: "memory")

__device__ __forceinline__ void mma16(float* c, uint4 a, uint32_t b0, uint32_t b1) {
    asm volatile("mma.sync.aligned.m16n8k16.row.col.f32.bf16.bf16.f32 "
        "{%0,%1,%2,%3}, {%4,%5,%6,%7}, {%8,%9}, {%0,%1,%2,%3};"
        : "+f"(c[0]), "+f"(c[1]), "+f"(c[2]), "+f"(c[3])
        : "r"(a.x), "r"(a.y), "r"(a.z), "r"(a.w), "r"(b0), "r"(b1));
}

// ---------------------------------------------------------------------------
// 1) Compact valid columns — warp-per-2-batches, 2 block syncs total.
// ---------------------------------------------------------------------------
__global__ void compact_kernel(const int* __restrict__ log_mask,
                               const int* __restrict__ items,
                               const float* __restrict__ pop) {
    __shared__ int cnt[64];
    __shared__ int off[64];
    int t = threadIdx.x, w = t >> 5, lane = t & 31;

    #pragma unroll
    for (int s = 0; s < 2; s++) {
        int b = 2 * w + s;
        int c = 0;
        #pragma unroll
        for (int ch = 0; ch < 4; ch++) {
            int pos = ch * 32 + lane;
            int flag = 0;
            if (pos <= LSEQ) flag = (pos == LSEQ) ? 1 : (log_mask[b * LSEQ + pos] != 0);
            c += __popc(__ballot_sync(0xffffffffu, flag));
        }
        if (lane == 0) cnt[b] = c;
    }
    __syncthreads();

    if (w == 0) {
        int c0 = cnt[2 * lane], c1 = cnt[2 * lane + 1];
        int s = c0 + c1, sc = s;
        #pragma unroll
        for (int o = 1; o < 32; o <<= 1) {
            int u = __shfl_up_sync(0xffffffffu, sc, o);
            if (lane >= o) sc += u;
        }
        int base = sc - s;
        off[2 * lane] = base;
        off[2 * lane + 1] = base + c0;
        if (lane == 31) g_nv = sc;
    }
    __syncthreads();

    #pragma unroll
    for (int s = 0; s < 2; s++) {
        int b = 2 * w + s;
        int o = off[b];
        #pragma unroll
        for (int ch = 0; ch < 4; ch++) {
            int pos = ch * 32 + lane;
            int flag = 0;
            if (pos <= LSEQ) flag = (pos == LSEQ) ? 1 : (log_mask[b * LSEQ + pos] != 0);
            unsigned bal = __ballot_sync(0xffffffffu, flag);
            if (flag) {
                int slot = o + __popc(bal & ((1u << lane) - 1u));
                int k = b * LP1 + pos;
                g_colid[slot] = k;
                int id = items[k];
                g_itemid[slot] = id;
                g_addterm[slot] = -log2f(pop[id]);
            }
            o += __popc(bal);
        }
    }
}

// ---------------------------------------------------------------------------
// 2) Fused dup-mask + bf16 fragment-prep + target (all depend only on compact).
//    blocks [0,64): dup mask; [64,164): A frags; [164,268): B frags;
//    [268,368): exact fp32 target logits.
// ---------------------------------------------------------------------------
#define AB_BLK  (NROW * 8 / 512)     // 100
#define BB_BLK  (NCOLP * 8 / 512)    // 104
#define TG_BLK  (NROW / 64)          // 100
#define FUSE_BLOCKS (BSZ + AB_BLK + BB_BLK + TG_BLK)

__global__ void dupprep_kernel(const int* __restrict__ items,
                               const float* __restrict__ prec,
                               const float* __restrict__ embs,
                               const float* __restrict__ pop,
                               const int* __restrict__ log_mask) {
    int blk = blockIdx.x;
    int t = threadIdx.x;
    if (blk < BSZ) {
        __shared__ int ids[LP1];
        int i = blk;
        if (t < LP1) ids[t] = items[i * LP1 + t];
        __syncthreads();
        int nv = g_nv;
        int nvp = (nv + 127) & ~127;
        const float NINF = __int_as_float(0xff800000);
        for (int kv = t; kv < nvp; kv += 512) {
            float out = NINF;
            if (kv < nv) {
                int id = g_itemid[kv];
                bool dup = false;
                #pragma unroll 4
                for (int j = 0; j < LP1; j++) dup |= (id == ids[j]);
                out = dup ? NINF : g_addterm[kv];
            }
            g_keep[i * NCOLP + kv] = out;
        }
    } else if (blk < BSZ + AB_BLK) {
        // A fragments: idx -> (mt128, b16, kt, lane)
        int iA = (blk - BSZ) * 512 + t;
        int lane = iA & 31;
        int kt = (iA >> 5) & 3;
        int b16 = (iA >> 7) & 7;
        int mt128 = iA >> 10;
        int g = lane >> 2, tig = lane & 3;
        int r0 = mt128 * 128 + b16 * 16 + g;
        int k0 = kt * 16 + tig * 2;
        const float* ar = prec + r0 * DIM;
        const float* ar8 = ar + 8 * DIM;
        uint4 v;
        v.x = pk2(ar[k0] * LOG2E, ar[k0 + 1] * LOG2E);      // a0: row g,   k0..k0+1
        v.y = pk2(ar8[k0] * LOG2E, ar8[k0 + 1] * LOG2E);    // a1: row g+8
        v.z = pk2(ar[k0 + 8] * LOG2E, ar[k0 + 9] * LOG2E);  // a2: row g,   k0+8..9
        v.w = pk2(ar8[k0 + 8] * LOG2E, ar8[k0 + 9] * LOG2E);// a3: row g+8
        g_Afrag4[iA] = v;
    } else if (blk < BSZ + AB_BLK + BB_BLK) {
        // B fragments: idx -> (ktile, cc, kt, lane)
        int iB = (blk - BSZ - AB_BLK) * 512 + t;
        int lane = iB & 31;
        int kt = (iB >> 5) & 3;
        int cc = (iB >> 7) & 7;
        int ktile = iB >> 10;
        int g = lane >> 2, tig = lane & 3;
        int nv = g_nv;
        int c0 = ktile * 128 + cc * 16 + g;   // n-group 0 column
        int c1 = c0 + 8;                      // n-group 1 column
        int k0 = kt * 16 + tig * 2;
        uint4 v = make_uint4(0u, 0u, 0u, 0u);
        if (c0 < nv) {
            const float* e = embs + g_colid[c0] * DIM;
            v.x = pk2(e[k0], e[k0 + 1]);          // b0 of n-group 0
            v.y = pk2(e[k0 + 8], e[k0 + 9]);      // b1 of n-group 0
        }
        if (c1 < nv) {
            const float* e = embs + g_colid[c1] * DIM;
            v.z = pk2(e[k0], e[k0 + 1]);          // b0 of n-group 1
            v.w = pk2(e[k0 + 8], e[k0 + 9]);      // b1 of n-group 1
        }
        g_Bfrag4[iB] = v;
    } else {
        // target logits: 8 threads per row, 64 rows per block (exact fp32)
        int rloc = t >> 3, sub = t & 7;
        int r = (blk - BSZ - AB_BLK - BB_BLK) * 64 + rloc;
        int i = r / LSEQ, j = r - i * LSEQ;
        int pos = j + 1;
        int valid = (pos == LSEQ) ? 1 : (log_mask[i * LSEQ + pos] != 0);
        int tc = i * LP1 + pos;
        const float4* p4 = (const float4*)(prec + r * DIM);
        const float4* e4 = (const float4*)(embs + tc * DIM);
        float4 a0 = p4[sub], b0 = e4[sub], a1 = p4[sub + 8], b1 = e4[sub + 8];
        float s = a0.x * b0.x + a0.y * b0.y + a0.z * b0.z + a0.w * b0.w
                + a1.x * b1.x + a1.y * b1.y + a1.z * b1.z + a1.w * b1.w;
        s += __shfl_down_sync(0xffffffffu, s, 4);
        s += __shfl_down_sync(0xffffffffu, s, 2);
        s += __shfl_down_sync(0xffffffffu, s, 1);
        if (sub == 0) g_tgt[r] = valid ? (s - logf(pop[items[tc]])) : NEG10K;
    }
}

// ---------------------------------------------------------------------------
// 3) Main: bf16 m16n8k16 mma.sync GEMM + fused exp2 row-sums.
//    512 threads, 16 warps (4 row-groups x 4 col-groups), 3-deep cp.async
//    ring, 2 CTAs/SM. In-CTA reduction collapses the 4 col-group slices.
// ---------------------------------------------------------------------------
// smem floats: A 4096 | B 3*4096 | K 3*384 | sred 512
#define SMEM_BYTES ((16384 + 1152 + 512) * 4)

__global__ __launch_bounds__(512, 2)
void main_kernel() {
    extern __shared__ float sm[];
    uint4* As4 = (uint4*)sm;                        // 1024 uint4 (16KB)
    uint4* Bs4[3] = {(uint4*)(sm + 4096), (uint4*)(sm + 8192), (uint4*)(sm + 12288)};
    float* Ks[3] = {sm + 16384, sm + 16384 + 384, sm + 16384 + 768};
    float* sred = sm + 16384 + 1152;                // [4][128]
    const uint32_t su = smem_u32(sm);
    const uint32_t Bu[3] = {su + 16384, su + 32768, su + 49152};
    const uint32_t Ku[3] = {su + 65536, su + 65536 + 1536, su + 65536 + 3072};

    const int t = threadIdx.x;
    const int w = t >> 5, lane = t & 31;
    const int g = lane >> 2, tig = lane & 3;
    const int rg = w >> 2;                   // row group 0..3 (32 rows each)
    const int wcol = w & 3;                  // col group 0..3 (32 cols each)
    const int m0 = blockIdx.x * 128;
    const int ch = blockIdx.y;
    const int nv = g_nv;
    const int T = (nv + 127) >> 7;
    const int ntiles = (T > ch) ? ((T - ch + NCH - 1) / NCH) : 0;
    const int bfirst = m0 / LSEQ;

    int bl[2][2];
    #pragma unroll
    for (int mt = 0; mt < 2; mt++)
        #pragma unroll
        for (int h = 0; h < 2; h++)
            bl[mt][h] = (m0 + rg * 32 + mt * 16 + g + h * 8) / LSEQ - bfirst;

    float rs[4] = {0.f, 0.f, 0.f, 0.f};

    if (ntiles > 0) {
        auto stageB = [&](int tile, int buf) {
            const uint4* Bg = g_Bfrag4 + (size_t)tile * 1024;
            cp16(Bu[buf] + t * 16, Bg + t);
            cp16(Bu[buf] + (t + 512) * 16, Bg + t + 512);
            if (t < 96) {
                int b = t >> 5, q = t & 31;
                int bg = min(bfirst + b, BSZ - 1);
                cp16(Ku[buf] + (b * 128 + q * 4) * 4,
                     g_keep + (size_t)bg * NCOLP + tile * 128 + q * 4);
            }
        };

        // prologue: A (once) + up to 3 B tiles
        {
            const uint4* Ag = g_Afrag4 + (size_t)blockIdx.x * 1024;
            cp16(su + t * 16, Ag + t);
            cp16(su + (t + 512) * 16, Ag + t + 512);
        }
        stageB(ch, 0);
        CP_COMMIT();
        int committed = 1;
        if (ntiles > 1) { stageB(ch + NCH, 1); CP_COMMIT(); committed = 2; }
        if (ntiles > 2) { stageB(ch + 2 * NCH, 2); CP_COMMIT(); committed = 3; }

        const uint4* a0p = As4 + (rg * 2 + 0) * 128 + lane;   // [b16][kt][lane]
        const uint4* a1p = As4 + (rg * 2 + 1) * 128 + lane;

        for (int ti = 0; ti < ntiles; ti++) {
            int rem = committed - ti - 1;
            if (rem >= 2) CP_WAIT2(); else if (rem == 1) CP_WAIT1(); else CP_WAIT0();
            __syncthreads();

            int buf = ti - (ti / 3) * 3;
            const uint4* B4 = Bs4[buf];
            const float* KP = Ks[buf];

            #pragma unroll
            for (int cc2 = 0; cc2 < 2; cc2++) {
                const int cc = wcol * 2 + cc2;
                const uint4* bp = B4 + cc * 128 + lane;
                float c[2][2][4];
                #pragma unroll
                for (int mt = 0; mt < 2; mt++)
                    #pragma unroll
                    for (int nt = 0; nt < 2; nt++)
                        #pragma unroll
                        for (int q = 0; q < 4; q++) c[mt][nt][q] = 0.f;

                #pragma unroll
                for (int kt = 0; kt < 4; kt++) {
                    uint4 a0 = a0p[kt * 32];
                    uint4 a1 = a1p[kt * 32];
                    uint4 b = bp[kt * 32];
                    mma16(c[0][0], a0, b.x, b.y);
                    mma16(c[0][1], a0, b.z, b.w);
                    mma16(c[1][0], a1, b.x, b.y);
                    mma16(c[1][1], a1, b.z, b.w);
                }

                const int C = cc * 16;
                #pragma unroll
                for (int mt = 0; mt < 2; mt++) {
                    #pragma unroll
                    for (int nt = 0; nt < 2; nt++) {
                        int col = C + nt * 8 + 2 * tig;
                        float2 k0 = *(const float2*)(KP + bl[mt][0] * 128 + col);
                        float2 k1 = *(const float2*)(KP + bl[mt][1] * 128 + col);
                        rs[mt * 2 + 0] += ex2f(c[mt][nt][0] + k0.x) + ex2f(c[mt][nt][1] + k0.y);
                        rs[mt * 2 + 1] += ex2f(c[mt][nt][2] + k1.x) + ex2f(c[mt][nt][3] + k1.y);
                    }
                }
            }

            __syncthreads();
            if (ti + 3 < ntiles) { stageB(ch + (ti + 3) * NCH, buf); CP_COMMIT(); committed++; }
        }
    }

    // reduce over the 4 tig lanes of each row
    #pragma unroll
    for (int q = 0; q < 4; q++) {
        rs[q] += __shfl_xor_sync(0xffffffffu, rs[q], 1);
        rs[q] += __shfl_xor_sync(0xffffffffu, rs[q], 2);
    }
    if (tig == 0) {
        #pragma unroll
        for (int mt = 0; mt < 2; mt++)
            #pragma unroll
            for (int h = 0; h < 2; h++)
                sred[wcol * 128 + rg * 32 + mt * 16 + h * 8 + g] = rs[mt * 2 + h];
    }
    __syncthreads();
    // combine the 4 col-group slices; one partS entry per (row, chunk)
    if (t < 128) {
        float s = (sred[t] + sred[t + 128]) + (sred[t + 256] + sred[t + 384]);
        g_partS[(m0 + t) * NCH + ch] = s;
    }
}

// ---------------------------------------------------------------------------
// 4) Two-stage deterministic reduction
// ---------------------------------------------------------------------------
__global__ void reduce1_kernel(const int* __restrict__ log_mask) {
    __shared__ double sn[256];
    __shared__ double sd[256];
    int t = threadIdx.x;
    int r = blockIdx.x * 256 + t;
    const float2* p = (const float2*)(g_partS + (size_t)r * NCH);
    float2 v0 = p[0], v1 = p[1], v2 = p[2];
    float S = (v0.x + v0.y) + (v1.x + v1.y) + (v2.x + v2.y);
    float tv = g_tgt[r];
    S += __expf(tv);
    float nll = (S > 0.f) ? (logf(S) - tv) : logf((float)NCOL);
    bool wv = (log_mask[r] != 0);
    sn[t] = wv ? (double)nll : 0.0;
    sd[t] = wv ? 1.0 : 0.0;
    __syncthreads();
    for (int o = 128; o > 0; o >>= 1) {
        if (t < o) { sn[t] += sn[t + o]; sd[t] += sd[t + o]; }
        __syncthreads();
    }
    if (t == 0) { g_rn[blockIdx.x] = sn[0]; g_rd[blockIdx.x] = sd[0]; }
}

__global__ void reduce2_kernel(float* __restrict__ out) {
    __shared__ double sn[32];
    __shared__ double sd[32];
    int t = threadIdx.x;
    sn[t] = (t < 25) ? g_rn[t] : 0.0;
    sd[t] = (t < 25) ? g_rd[t] : 0.0;
    __syncthreads();
    for (int o = 16; o > 0; o >>= 1) {
        if (t < o) { sn[t] += sn[t + o]; sd[t] += sd[t + o]; }
        __syncthreads();
    }
    if (t == 0) out[0] = (float)(sn[0] / sd[0]);
}

// ---------------------------------------------------------------------------
extern "C" void kernel_launch(void* const* d_in, const int* in_sizes, int n_in,
                              void* d_out, int out_size) {
    const float* prec  = (const float*)d_in[0];  // [6400, 64]
    const float* embs  = (const float*)d_in[1];  // [6464, 64]
    const float* pop   = (const float*)d_in[2];  // [100001]
    const int*   items = (const int*)d_in[3];    // [6464]
    const int*   lmask = (const int*)d_in[4];    // [64, 100]
    float* out = (float*)d_out;

    cudaFuncSetAttribute(main_kernel, cudaFuncAttributeMaxDynamicSharedMemorySize,
                         SMEM_BYTES);

    compact_kernel<<<1, 1024>>>(lmask, items, pop);
    dupprep_kernel<<<FUSE_BLOCKS, 512>>>(items, prec, embs, pop, lmask);
    main_kernel<<<dim3(NROW / 128, NCH), 512, SMEM_BYTES>>>();
    reduce1_kernel<<<NROW / 256, 256>>>(lmask);
    reduce2_kernel<<<1, 32>>>(out);
}